// round 1
// baseline (speedup 1.0000x reference)
#include <cuda_runtime.h>
#include <math.h>

#define Bb   2
#define Ss   1024
#define Vv   32000
#define Dd   256
#define Mm   256
#define Ww   8
#define HLh  1024
#define HCh  1024
#define Rr   (Bb*Ss)          // 2048
#define F1   (Mm+Dd)          // 512
#define F2   (Ww*Dd)          // 2048

// ---------------- scratch (static device globals; no allocation) ------------
__device__ float g_x[Rr*Dd];          // 2 MB
__device__ float g_u[Rr*Mm];          // 2 MB
__device__ float g_feat[Rr*F1];       // 4 MB
__device__ float g_locin[Rr*F2];      // 16 MB
__device__ float g_h[Rr*HLh];         // 8 MB
__device__ float g_h2[Rr*HCh];        // 8 MB
__device__ float g_lin[Rr*Vv];        // 262 MB
__device__ float g_loc[Rr*Vv];        // 262 MB
__device__ float g_stats[Rr*6];
__device__ float g_gate[Rr];

// ---------------- embedding gather (also fills feat[:,M:]) -----------------
__global__ void gather_embed_kernel(const int* __restrict__ tok,
                                    const float* __restrict__ emb) {
    int r = blockIdx.x;
    int d = threadIdx.x;                 // D = 256 threads
    float v = emb[(size_t)tok[r] * Dd + d];
    g_x[r*Dd + d] = v;
    g_feat[(size_t)r*F1 + Mm + d] = v;
}

// ---------------- decay-bank scan: s_t = a*s_{t-1} + u_t --------------------
__global__ void scan_kernel(const float* __restrict__ decays) {
    int b = blockIdx.x;
    int m = threadIdx.x;                 // M = 256 threads
    float a = decays[m];
    float s = 0.f;
    for (int t = 0; t < Ss; t++) {
        int r = b*Ss + t;
        s = a*s + g_u[(size_t)r*Mm + m];
        g_feat[(size_t)r*F1 + m] = s;
    }
}

// ---------------- build causal window features ------------------------------
__global__ void build_loc_kernel() {
    int idx = blockIdx.x * blockDim.x + threadIdx.x;   // over R*W*D = 4,194,304
    if (idx >= Rr*Ww*Dd) return;
    int d = idx % Dd;
    int w = (idx / Dd) % Ww;
    int r = idx / (Ww*Dd);
    int s = r % Ss, b = r / Ss;
    int ss = s - (Ww-1) + w;
    g_locin[idx] = (ss >= 0) ? g_x[((size_t)(b*Ss + ss))*Dd + d] : 0.f;
}

// ---------------- 128x128x8 register-tiled SGEMM ---------------------------
// C[RrxN] = A[RrxK] @ B[KxN] (+bias) (optional relu). All dims divide tiles.
#define BM 128
#define BN 128
#define BK 8

template<bool RELU>
__global__ void __launch_bounds__(256) sgemm_kernel(
        const float* __restrict__ A, const float* __restrict__ Bm,
        const float* __restrict__ bias, float* __restrict__ C,
        int K, int N) {
    __shared__ float As[BK][BM];
    __shared__ float Bs[BK][BN];

    int tid = threadIdx.x;
    int tx = tid & 15;        // 0..15  -> 8 cols each
    int ty = tid >> 4;        // 0..15  -> 8 rows each
    int mBase = blockIdx.y * BM;
    int nBase = blockIdx.x * BN;

    // A loads: thread -> (row aM, k aK..aK+3)
    int aM = tid >> 1;
    int aK = (tid & 1) * 4;
    // B loads: thread -> (k bK, cols bN..bN+3)
    int bK = tid >> 5;
    int bN = (tid & 31) * 4;

    const float* Aptr = A + (size_t)(mBase + aM) * K + aK;
    const float* Bptr = Bm + (size_t)bK * N + nBase + bN;

    float acc[8][8];
#pragma unroll
    for (int i = 0; i < 8; i++)
#pragma unroll
        for (int j = 0; j < 8; j++) acc[i][j] = 0.f;

    for (int kt = 0; kt < K; kt += BK) {
        float4 av = *(const float4*)Aptr;  Aptr += BK;
        float4 bv = *(const float4*)Bptr;  Bptr += (size_t)BK * N;
        As[aK+0][aM] = av.x; As[aK+1][aM] = av.y;
        As[aK+2][aM] = av.z; As[aK+3][aM] = av.w;
        *(float4*)&Bs[bK][bN] = bv;
        __syncthreads();

        float ar[8], br[8];
#pragma unroll
        for (int k = 0; k < BK; k++) {
#pragma unroll
            for (int i = 0; i < 8; i++) ar[i] = As[k][ty*8 + i];
#pragma unroll
            for (int j = 0; j < 8; j++) br[j] = Bs[k][tx*8 + j];
#pragma unroll
            for (int i = 0; i < 8; i++)
#pragma unroll
                for (int j = 0; j < 8; j++)
                    acc[i][j] = fmaf(ar[i], br[j], acc[i][j]);
        }
        __syncthreads();
    }

#pragma unroll
    for (int i = 0; i < 8; i++) {
        int m = mBase + ty*8 + i;
        float* Crow = C + (size_t)m * N + nBase + tx*8;
#pragma unroll
        for (int j = 0; j < 8; j++) {
            float v = acc[i][j];
            if (bias) v += bias[nBase + tx*8 + j];
            if (RELU) v = fmaxf(v, 0.f);
            Crow[j] = v;
        }
    }
}

// ---------------- per-row stats (mean, max, std) per branch ----------------
__global__ void stats_kernel() {
    int r  = blockIdx.x;
    int br = blockIdx.y;                 // 0 = lin, 1 = loc
    const float* z = (br ? g_loc : g_lin) + (size_t)r * Vv;
    int tid = threadIdx.x;
    float s = 0.f, sq = 0.f, mx = -3.4e38f;
    for (int i = tid; i < Vv; i += 256) {
        float v = z[i];
        s += v; sq += v*v; mx = fmaxf(mx, v);
    }
    __shared__ float ss[256], ssq[256], smx[256];
    ss[tid] = s; ssq[tid] = sq; smx[tid] = mx;
    __syncthreads();
    for (int off = 128; off > 0; off >>= 1) {
        if (tid < off) {
            ss[tid]  += ss[tid+off];
            ssq[tid] += ssq[tid+off];
            smx[tid]  = fmaxf(smx[tid], smx[tid+off]);
        }
        __syncthreads();
    }
    if (tid == 0) {
        float mean = ss[0] / (float)Vv;
        float var  = ssq[0] / (float)Vv - mean*mean;
        var = fmaxf(var, 0.f);
        float* st = g_stats + (size_t)r*6 + br*3;
        st[0] = mean;
        st[1] = smx[0];
        st[2] = sqrtf(var);
    }
}

// ---------------- gate: sigmoid(stats . gate_w + gate_b) -------------------
__global__ void gate_kernel(const float* __restrict__ gw,
                            const float* __restrict__ gb) {
    int r = blockIdx.x * blockDim.x + threadIdx.x;
    if (r >= Rr) return;
    const float* st = g_stats + (size_t)r*6;
    float acc = gb[0];
#pragma unroll
    for (int k = 0; k < 6; k++) acc += st[k] * gw[k];
    g_gate[r] = 1.f / (1.f + expf(-acc));
}

// ---------------- mix: out = g*lin + (1-g)*loc ------------------------------
__global__ void mix_kernel(float* __restrict__ out) {
    int r = blockIdx.y;
    int c = blockIdx.x * blockDim.x + threadIdx.x;   // V = 32000 = 125*256
    size_t i = (size_t)r * Vv + c;
    float g = g_gate[r];
    out[i] = g * g_lin[i] + (1.f - g) * g_loc[i];
}

// ---------------- launch ----------------------------------------------------
extern "C" void kernel_launch(void* const* d_in, const int* in_sizes, int n_in,
                              void* d_out, int out_size) {
    const int*   tokens  = (const int*)  d_in[0];
    const float* emb     = (const float*)d_in[1];
    const float* in_proj = (const float*)d_in[2];
    const float* decays  = (const float*)d_in[3];
    const float* w1      = (const float*)d_in[4];
    const float* b1      = (const float*)d_in[5];
    const float* w2      = (const float*)d_in[6];
    const float* b2      = (const float*)d_in[7];
    const float* lw1     = (const float*)d_in[8];
    const float* lb1     = (const float*)d_in[9];
    const float* lw2     = (const float*)d_in[10];
    const float* lb2     = (const float*)d_in[11];
    const float* gate_w  = (const float*)d_in[12];
    const float* gate_b  = (const float*)d_in[13];
    float* out = (float*)d_out;

    float *gx, *gu, *gfeat, *glocin, *gh, *gh2, *glin, *gloc;
    cudaGetSymbolAddress((void**)&gx,     g_x);
    cudaGetSymbolAddress((void**)&gu,     g_u);
    cudaGetSymbolAddress((void**)&gfeat,  g_feat);
    cudaGetSymbolAddress((void**)&glocin, g_locin);
    cudaGetSymbolAddress((void**)&gh,     g_h);
    cudaGetSymbolAddress((void**)&gh2,    g_h2);
    cudaGetSymbolAddress((void**)&glin,   g_lin);
    cudaGetSymbolAddress((void**)&gloc,   g_loc);

    // 1) embedding gather (fills g_x and feat[:, M:])
    gather_embed_kernel<<<Rr, Dd>>>(tokens, emb);

    // 2) u = x @ in_proj   [2048,256]x[256,256]
    sgemm_kernel<false><<<dim3(Mm/BN, Rr/BM), 256>>>(gx, in_proj, nullptr, gu, Dd, Mm);

    // 3) decay scan -> feat[:, :M]
    scan_kernel<<<Bb, Mm>>>(decays);

    // 4) window features
    build_loc_kernel<<<(Rr*Ww*Dd + 255)/256, 256>>>();

    // 5) h = relu(feat @ w1 + b1)     [2048,512]x[512,1024]
    sgemm_kernel<true><<<dim3(HLh/BN, Rr/BM), 256>>>(gfeat, w1, b1, gh, F1, HLh);

    // 6) h2 = relu(loc @ lw1 + lb1)   [2048,2048]x[2048,1024]
    sgemm_kernel<true><<<dim3(HCh/BN, Rr/BM), 256>>>(glocin, lw1, lb1, gh2, F2, HCh);

    // 7) lin_logits = h @ w2 + b2     [2048,1024]x[1024,32000]
    sgemm_kernel<false><<<dim3(Vv/BN, Rr/BM), 256>>>(gh, w2, b2, glin, HLh, Vv);

    // 8) loc_logits = h2 @ lw2 + lb2  [2048,1024]x[1024,32000]
    sgemm_kernel<false><<<dim3(Vv/BN, Rr/BM), 256>>>(gh2, lw2, lb2, gloc, HCh, Vv);

    // 9) per-row stats, gate, mix
    stats_kernel<<<dim3(Rr, 2), 256>>>();
    gate_kernel<<<(Rr + 255)/256, 256>>>(gate_w, gate_b);
    mix_kernel<<<dim3(Vv/256, Rr), 256>>>(out);
}

// round 4
// speedup vs baseline: 2.2667x; 2.2667x over previous
#include <cuda_runtime.h>
#include <cuda_bf16.h>
#include <cstdint>
#include <math.h>

#define Bb   2
#define Ss   1024
#define Vv   32000
#define Dd   256
#define Mm   256
#define Ww   8
#define HLh  1024
#define HCh  1024
#define Rr   (Bb*Ss)          // 2048
#define F1   (Mm+Dd)          // 512
#define F2   (Ww*Dd)          // 2048

// ======================= helpers ===========================================
__device__ __forceinline__ uint32_t smem_u32(const void* p) {
    uint32_t a;
    asm("{ .reg .u64 t; cvta.to.shared.u64 t, %1; cvt.u32.u64 %0, t; }" : "=r"(a) : "l"(p));
    return a;
}
#define CP_ASYNC16(dst, src) \
    asm volatile("cp.async.cg.shared.global [%0], [%1], 16;" :: "r"(dst), "l"(src))
#define CP_COMMIT() asm volatile("cp.async.commit_group;" ::: "memory")
#define CP_WAIT(n)  asm volatile("cp.async.wait_group %0;" :: "n"(n) : "memory")

__device__ __forceinline__ void ldmx4(uint32_t* r, uint32_t addr) {
    asm volatile("ldmatrix.sync.aligned.m8n8.x4.shared.b16 {%0,%1,%2,%3}, [%4];"
        : "=r"(r[0]), "=r"(r[1]), "=r"(r[2]), "=r"(r[3]) : "r"(addr));
}
__device__ __forceinline__ void mma16816(float* c, const uint32_t* a, const uint32_t* b) {
    asm volatile(
        "mma.sync.aligned.m16n8k16.row.col.f32.bf16.bf16.f32 "
        "{%0,%1,%2,%3}, {%4,%5,%6,%7}, {%8,%9}, {%0,%1,%2,%3};"
        : "+f"(c[0]), "+f"(c[1]), "+f"(c[2]), "+f"(c[3])
        : "r"(a[0]), "r"(a[1]), "r"(a[2]), "r"(a[3]), "r"(b[0]), "r"(b[1]));
}

// ======================= scratch ===========================================
__device__ float g_x[Rr*Dd];
__device__ float g_u[Rr*Mm];
__device__ float g_feat[Rr*F1];
__device__ float g_locin[Rr*F2];
__device__ float g_lin[(size_t)Rr*Vv];
__device__ float g_loc[(size_t)Rr*Vv];
__device__ float g_stats[Rr*6];
__device__ float g_gate[Rr];
__device__ __nv_bfloat16 g_feat_hi[Rr*F1],  g_feat_lo[Rr*F1];
__device__ __nv_bfloat16 g_locin_hi[Rr*F2], g_locin_lo[Rr*F2];
__device__ __nv_bfloat16 g_h_hi[Rr*HLh],    g_h_lo[Rr*HLh];
__device__ __nv_bfloat16 g_h2_hi[Rr*HCh],   g_h2_lo[Rr*HCh];
__device__ __nv_bfloat16 g_w1t_hi[HLh*F1],  g_w1t_lo[HLh*F1];
__device__ __nv_bfloat16 g_lw1t_hi[HCh*F2], g_lw1t_lo[HCh*F2];
__device__ __nv_bfloat16 g_w2t_hi[(size_t)Vv*HLh],  g_w2t_lo[(size_t)Vv*HLh];
__device__ __nv_bfloat16 g_lw2t_hi[(size_t)Vv*HCh], g_lw2t_lo[(size_t)Vv*HCh];

// ======================= small kernels =====================================
__global__ void gather_embed_kernel(const int* __restrict__ tok,
                                    const float* __restrict__ emb) {
    int r = blockIdx.x, d = threadIdx.x;
    float v = emb[(size_t)tok[r] * Dd + d];
    g_x[r*Dd + d] = v;
    g_feat[(size_t)r*F1 + Mm + d] = v;
}

__global__ void scan_kernel(const float* __restrict__ decays) {
    int b = blockIdx.x, m = threadIdx.x;
    float a = decays[m], s = 0.f;
    for (int t = 0; t < Ss; t++) {
        int r = b*Ss + t;
        s = a*s + g_u[(size_t)r*Mm + m];
        g_feat[(size_t)r*F1 + m] = s;
    }
}

__global__ void build_loc_kernel() {
    int idx = blockIdx.x * blockDim.x + threadIdx.x;
    if (idx >= Rr*Ww*Dd) return;
    int d = idx % Dd, w = (idx / Dd) % Ww, r = idx / (Ww*Dd);
    int s = r % Ss, b = r / Ss;
    int ss = s - (Ww-1) + w;
    g_locin[idx] = (ss >= 0) ? g_x[((size_t)(b*Ss + ss))*Dd + d] : 0.f;
}

__global__ void conv_split_kernel(const float* __restrict__ in,
                                  __nv_bfloat16* __restrict__ hi,
                                  __nv_bfloat16* __restrict__ lo, int n4) {
    int i = blockIdx.x * blockDim.x + threadIdx.x;
    if (i >= n4) return;
    float4 v = ((const float4*)in)[i];
    __nv_bfloat16 h0 = __float2bfloat16(v.x), h1 = __float2bfloat16(v.y);
    __nv_bfloat16 h2 = __float2bfloat16(v.z), h3 = __float2bfloat16(v.w);
    __nv_bfloat162 H0 = {h0, h1}, H1 = {h2, h3};
    __nv_bfloat162 L0 = {__float2bfloat16(v.x - __bfloat162float(h0)),
                         __float2bfloat16(v.y - __bfloat162float(h1))};
    __nv_bfloat162 L1 = {__float2bfloat16(v.z - __bfloat162float(h2)),
                         __float2bfloat16(v.w - __bfloat162float(h3))};
    ((__nv_bfloat162*)hi)[2*i]   = H0;  ((__nv_bfloat162*)hi)[2*i+1] = H1;
    ((__nv_bfloat162*)lo)[2*i]   = L0;  ((__nv_bfloat162*)lo)[2*i+1] = L1;
}

// transpose+split: W[K,N] fp32 row-major -> Wt hi/lo [N,K] bf16
__global__ void wtconv_kernel(const float* __restrict__ W,
                              __nv_bfloat16* __restrict__ hi,
                              __nv_bfloat16* __restrict__ lo, int K, int N) {
    __shared__ float t[32][33];
    int n0 = blockIdx.x * 32, k0 = blockIdx.y * 32;
    int tx = threadIdx.x & 31, ty = threadIdx.x >> 5;
#pragma unroll
    for (int r = 0; r < 4; r++)
        t[ty + 8*r][tx] = W[(size_t)(k0 + ty + 8*r) * N + n0 + tx];
    __syncthreads();
#pragma unroll
    for (int r = 0; r < 4; r++) {
        int n = n0 + ty + 8*r, k = k0 + tx;
        float v = t[tx][ty + 8*r];
        __nv_bfloat16 h = __float2bfloat16(v);
        hi[(size_t)n*K + k] = h;
        lo[(size_t)n*K + k] = __float2bfloat16(v - __bfloat162float(h));
    }
}

// ======================= HMMA (mma.sync) GEMM ==============================
// C[2048 x Ntot] = (Ahi+Alo)[M,K] @ (Bhi+Blo)[Ntot,K]^T, 3-term bf16 split.
// OUTMODE 0: Cf = acc + bias.  OUTMODE 1: relu(acc+bias) -> Chi/Clo bf16.
// CTA: 128x128x32, 256 threads, 8 warps (4 M x 2 N), warp tile 32x64.
#define STAGES 3
#define ROWB   80                 // padded smem row: 64B data + 16B pad
#define ABYTES (128*ROWB)         // 10240
#define STAGEB (2*ABYTES)         // 20480

template<int OUTMODE>
__global__ void __launch_bounds__(256, 2) hmma_kernel(
        const __nv_bfloat16* __restrict__ Ahi, const __nv_bfloat16* __restrict__ Alo,
        const __nv_bfloat16* __restrict__ Bhi, const __nv_bfloat16* __restrict__ Blo,
        const float* __restrict__ bias,
        float* __restrict__ Cf,
        __nv_bfloat16* __restrict__ Chi, __nv_bfloat16* __restrict__ Clo,
        int K, int Ntot) {
    extern __shared__ char smem[];
    const uint32_t sb = smem_u32(smem);
    const int tid = threadIdx.x;
    const int wid = tid >> 5, lid = tid & 31;
    const int wm = wid & 3, wn = wid >> 2;          // warp grid 4 x 2
    const int mBase = blockIdx.x * 128;
    const int nBase = blockIdx.y * 128;

    const int KC = K / 32;       // stages per split pass
    const int NC = 3 * KC;       // total stages (hi*hi, lo*hi, hi*lo)

    float acc[2][8][4];
#pragma unroll
    for (int i = 0; i < 2; i++)
#pragma unroll
        for (int j = 0; j < 8; j++)
#pragma unroll
            for (int q = 0; q < 4; q++) acc[i][j][q] = 0.f;

    auto load_tile = [&](int c, int s) {
        int pass = c / KC, kc = c - pass * KC;
        const __nv_bfloat16* Ap = (pass == 1) ? Alo : Ahi;
        const __nv_bfloat16* Bp = (pass == 2) ? Blo : Bhi;
        int kof = kc * 32;
        uint32_t ab = sb + s * STAGEB;
        uint32_t bb = ab + ABYTES;
#pragma unroll
        for (int i = 0; i < 2; i++) {        // A: 128 rows x 4 chunks(16B)
            int id = tid + i * 256;
            int row = id >> 2, q = id & 3;
            CP_ASYNC16(ab + row*ROWB + q*16,
                       Ap + (size_t)(mBase + row) * K + kof + q*8);
        }
#pragma unroll
        for (int i = 0; i < 2; i++) {        // B(t): 128 rows x 4 chunks
            int id = tid + i * 256;
            int row = id >> 2, q = id & 3;
            CP_ASYNC16(bb + row*ROWB + q*16,
                       Bp + (size_t)(nBase + row) * K + kof + q*8);
        }
    };

    // prologue: prefetch STAGES-1 tiles
#pragma unroll
    for (int s = 0; s < STAGES - 1; s++) {
        load_tile(s, s);
        CP_COMMIT();
    }

    // lane addressing for ldmatrix
    const int aRow = (lid & 7) + ((lid >> 3) & 1) * 8;    // + frag base
    const int aKb  = (lid >> 4) * 16;
    const int bRow = (lid & 7) + ((lid >> 4) & 1) * 8;
    const int bKb  = ((lid >> 3) & 1) * 16;

    for (int c = 0; c < NC; c++) {
        CP_WAIT(STAGES - 2);
        __syncthreads();
        if (c + STAGES - 1 < NC) load_tile(c + STAGES - 1, (c + STAGES - 1) % STAGES);
        CP_COMMIT();

        uint32_t ab = sb + (c % STAGES) * STAGEB;
        uint32_t bb = ab + ABYTES;
#pragma unroll
        for (int ks = 0; ks < 2; ks++) {
            uint32_t afr[2][4], bfr[4][4];
#pragma unroll
            for (int i = 0; i < 2; i++)
                ldmx4(afr[i], ab + (wm*32 + i*16 + aRow)*ROWB + ks*32 + aKb);
#pragma unroll
            for (int t = 0; t < 4; t++)
                ldmx4(bfr[t], bb + (wn*64 + t*16 + bRow)*ROWB + ks*32 + bKb);
#pragma unroll
            for (int i = 0; i < 2; i++)
#pragma unroll
                for (int j = 0; j < 8; j++)
                    mma16816(acc[i][j], afr[i], bfr[j >> 1] + (j & 1) * 2);
        }
        __syncthreads();
    }
    CP_WAIT(0);

    // ---- epilogue: direct register -> global (float2 / bf16x2 pairs) ----
    const int r0 = lid >> 2;
    const int c0 = (lid & 3) * 2;
#pragma unroll
    for (int i = 0; i < 2; i++) {
#pragma unroll
        for (int j = 0; j < 8; j++) {
            int col = nBase + wn*64 + j*8 + c0;
            int rowA = mBase + wm*32 + i*16 + r0;
            float2 bv = *(const float2*)(bias + col);
            float v0 = acc[i][j][0] + bv.x, v1 = acc[i][j][1] + bv.y;
            float v2 = acc[i][j][2] + bv.x, v3 = acc[i][j][3] + bv.y;
            if (OUTMODE == 0) {
                *(float2*)(Cf + (size_t)rowA * Ntot + col)       = make_float2(v0, v1);
                *(float2*)(Cf + (size_t)(rowA + 8) * Ntot + col) = make_float2(v2, v3);
            } else {
                v0 = fmaxf(v0, 0.f); v1 = fmaxf(v1, 0.f);
                v2 = fmaxf(v2, 0.f); v3 = fmaxf(v3, 0.f);
                __nv_bfloat16 h0 = __float2bfloat16(v0), h1 = __float2bfloat16(v1);
                __nv_bfloat16 h2 = __float2bfloat16(v2), h3 = __float2bfloat16(v3);
                *(__nv_bfloat162*)(Chi + (size_t)rowA * Ntot + col) = __nv_bfloat162{h0, h1};
                *(__nv_bfloat162*)(Chi + (size_t)(rowA+8) * Ntot + col) = __nv_bfloat162{h2, h3};
                *(__nv_bfloat162*)(Clo + (size_t)rowA * Ntot + col) =
                    __nv_bfloat162{__float2bfloat16(v0 - __bfloat162float(h0)),
                                   __float2bfloat16(v1 - __bfloat162float(h1))};
                *(__nv_bfloat162*)(Clo + (size_t)(rowA+8) * Ntot + col) =
                    __nv_bfloat162{__float2bfloat16(v2 - __bfloat162float(h2)),
                                   __float2bfloat16(v3 - __bfloat162float(h3))};
            }
        }
    }
}

// ======================= fp32 SGEMM (small u GEMM only) ====================
#define BM 128
#define BNs 128
#define BKs 8
__global__ void __launch_bounds__(256) sgemm_kernel(
        const float* __restrict__ A, const float* __restrict__ Bm,
        float* __restrict__ C, int K, int N) {
    __shared__ float As[BKs][BM];
    __shared__ float Bs2[BKs][BNs];
    int tid = threadIdx.x;
    int tx = tid & 15, ty = tid >> 4;
    int mBase = blockIdx.y * BM, nBase = blockIdx.x * BNs;
    int aM = tid >> 1, aK = (tid & 1) * 4;
    int bK = tid >> 5, bN = (tid & 31) * 4;
    const float* Aptr = A + (size_t)(mBase + aM) * K + aK;
    const float* Bptr = Bm + (size_t)bK * N + nBase + bN;
    float acc[8][8];
#pragma unroll
    for (int i = 0; i < 8; i++)
#pragma unroll
        for (int j = 0; j < 8; j++) acc[i][j] = 0.f;
    for (int kt = 0; kt < K; kt += BKs) {
        float4 av = *(const float4*)Aptr;  Aptr += BKs;
        float4 bv = *(const float4*)Bptr;  Bptr += (size_t)BKs * N;
        As[aK+0][aM] = av.x; As[aK+1][aM] = av.y;
        As[aK+2][aM] = av.z; As[aK+3][aM] = av.w;
        *(float4*)&Bs2[bK][bN] = bv;
        __syncthreads();
        float ar[8], br[8];
#pragma unroll
        for (int k = 0; k < BKs; k++) {
#pragma unroll
            for (int i = 0; i < 8; i++) ar[i] = As[k][ty*8 + i];
#pragma unroll
            for (int j = 0; j < 8; j++) br[j] = Bs2[k][tx*8 + j];
#pragma unroll
            for (int i = 0; i < 8; i++)
#pragma unroll
                for (int j = 0; j < 8; j++)
                    acc[i][j] = fmaf(ar[i], br[j], acc[i][j]);
        }
        __syncthreads();
    }
#pragma unroll
    for (int i = 0; i < 8; i++) {
        float* Crow = C + (size_t)(mBase + ty*8 + i) * N + nBase + tx*8;
#pragma unroll
        for (int j = 0; j < 8; j++) Crow[j] = acc[i][j];
    }
}

// ======================= stats / gate / mix ================================
__global__ void stats_kernel() {
    int r = blockIdx.x, br = blockIdx.y;
    const float* z = (br ? g_loc : g_lin) + (size_t)r * Vv;
    int tid = threadIdx.x;
    float s = 0.f, sq = 0.f, mx = -3.4e38f;
    for (int i = tid; i < Vv; i += 256) {
        float v = z[i];
        s += v; sq += v*v; mx = fmaxf(mx, v);
    }
    __shared__ float ss[256], ssq[256], smx[256];
    ss[tid] = s; ssq[tid] = sq; smx[tid] = mx;
    __syncthreads();
    for (int off = 128; off > 0; off >>= 1) {
        if (tid < off) {
            ss[tid] += ss[tid+off];
            ssq[tid] += ssq[tid+off];
            smx[tid] = fmaxf(smx[tid], smx[tid+off]);
        }
        __syncthreads();
    }
    if (tid == 0) {
        float mean = ss[0] / (float)Vv;
        float var = fmaxf(ssq[0] / (float)Vv - mean*mean, 0.f);
        float* st = g_stats + (size_t)r*6 + br*3;
        st[0] = mean; st[1] = smx[0]; st[2] = sqrtf(var);
    }
}

__global__ void gate_kernel(const float* __restrict__ gw, const float* __restrict__ gb) {
    int r = blockIdx.x * blockDim.x + threadIdx.x;
    if (r >= Rr) return;
    const float* st = g_stats + (size_t)r*6;
    float acc = gb[0];
#pragma unroll
    for (int k = 0; k < 6; k++) acc += st[k] * gw[k];
    g_gate[r] = 1.f / (1.f + expf(-acc));
}

__global__ void mix_kernel(float* __restrict__ out) {
    int r = blockIdx.y;
    int c = blockIdx.x * blockDim.x + threadIdx.x;
    size_t i = (size_t)r * Vv + c;
    float g = g_gate[r];
    out[i] = g * g_lin[i] + (1.f - g) * g_loc[i];
}

// ======================= launch ============================================
extern "C" void kernel_launch(void* const* d_in, const int* in_sizes, int n_in,
                              void* d_out, int out_size) {
    const int*   tokens  = (const int*)  d_in[0];
    const float* emb     = (const float*)d_in[1];
    const float* in_proj = (const float*)d_in[2];
    const float* decays  = (const float*)d_in[3];
    const float* w1      = (const float*)d_in[4];
    const float* b1      = (const float*)d_in[5];
    const float* w2      = (const float*)d_in[6];
    const float* b2      = (const float*)d_in[7];
    const float* lw1     = (const float*)d_in[8];
    const float* lb1     = (const float*)d_in[9];
    const float* lw2     = (const float*)d_in[10];
    const float* lb2     = (const float*)d_in[11];
    const float* gate_w  = (const float*)d_in[12];
    const float* gate_b  = (const float*)d_in[13];
    float* out = (float*)d_out;

    float *gx, *gu, *gfeat, *glocin, *glin, *gloc;
    cudaGetSymbolAddress((void**)&gx,     g_x);
    cudaGetSymbolAddress((void**)&gu,     g_u);
    cudaGetSymbolAddress((void**)&gfeat,  g_feat);
    cudaGetSymbolAddress((void**)&glocin, g_locin);
    cudaGetSymbolAddress((void**)&glin,   g_lin);
    cudaGetSymbolAddress((void**)&gloc,   g_loc);
    __nv_bfloat16 *fh, *fl, *lih, *lil, *hh, *hl, *h2h, *h2l;
    __nv_bfloat16 *w1h, *w1l, *lw1h, *lw1l, *w2h, *w2l, *lw2h, *lw2l;
    cudaGetSymbolAddress((void**)&fh,   g_feat_hi);
    cudaGetSymbolAddress((void**)&fl,   g_feat_lo);
    cudaGetSymbolAddress((void**)&lih,  g_locin_hi);
    cudaGetSymbolAddress((void**)&lil,  g_locin_lo);
    cudaGetSymbolAddress((void**)&hh,   g_h_hi);
    cudaGetSymbolAddress((void**)&hl,   g_h_lo);
    cudaGetSymbolAddress((void**)&h2h,  g_h2_hi);
    cudaGetSymbolAddress((void**)&h2l,  g_h2_lo);
    cudaGetSymbolAddress((void**)&w1h,  g_w1t_hi);
    cudaGetSymbolAddress((void**)&w1l,  g_w1t_lo);
    cudaGetSymbolAddress((void**)&lw1h, g_lw1t_hi);
    cudaGetSymbolAddress((void**)&lw1l, g_lw1t_lo);
    cudaGetSymbolAddress((void**)&w2h,  g_w2t_hi);
    cudaGetSymbolAddress((void**)&w2l,  g_w2t_lo);
    cudaGetSymbolAddress((void**)&lw2h, g_lw2t_hi);
    cudaGetSymbolAddress((void**)&lw2l, g_lw2t_lo);

    constexpr int SMEMB = STAGES * STAGEB;   // 61440
    cudaFuncSetAttribute(hmma_kernel<0>, cudaFuncAttributeMaxDynamicSharedMemorySize, SMEMB);
    cudaFuncSetAttribute(hmma_kernel<1>, cudaFuncAttributeMaxDynamicSharedMemorySize, SMEMB);

    // 1) embedding gather
    gather_embed_kernel<<<Rr, Dd>>>(tokens, emb);
    // 2) u = x @ in_proj (small fp32 GEMM)
    sgemm_kernel<<<dim3(Mm/BNs, Rr/BM), 256>>>(gx, in_proj, gu, Dd, Mm);
    // 3) decay scan -> feat[:, :M]
    scan_kernel<<<Bb, Mm>>>(decays);
    // 4) window features
    build_loc_kernel<<<(Rr*Ww*Dd + 255)/256, 256>>>();
    // 5) split conversions of activations
    conv_split_kernel<<<(Rr*F1/4 + 255)/256, 256>>>(gfeat,  fh,  fl,  Rr*F1/4);
    conv_split_kernel<<<(Rr*F2/4 + 255)/256, 256>>>(glocin, lih, lil, Rr*F2/4);
    // 6) weight transpose+split conversions
    wtconv_kernel<<<dim3(HLh/32, F1/32),  256>>>(w1,  w1h,  w1l,  F1,  HLh);
    wtconv_kernel<<<dim3(HCh/32, F2/32),  256>>>(lw1, lw1h, lw1l, F2,  HCh);
    wtconv_kernel<<<dim3(Vv/32,  HLh/32), 256>>>(w2,  w2h,  w2l,  HLh, Vv);
    wtconv_kernel<<<dim3(Vv/32,  HCh/32), 256>>>(lw2, lw2h, lw2l, HCh, Vv);
    // 7) h = relu(feat @ w1 + b1) -> split bf16
    hmma_kernel<1><<<dim3(Rr/128, HLh/128), 256, SMEMB>>>(
        fh, fl, w1h, w1l, b1, nullptr, hh, hl, F1, HLh);
    // 8) h2 = relu(loc @ lw1 + lb1) -> split bf16
    hmma_kernel<1><<<dim3(Rr/128, HCh/128), 256, SMEMB>>>(
        lih, lil, lw1h, lw1l, lb1, nullptr, h2h, h2l, F2, HCh);
    // 9) lin_logits = h @ w2 + b2
    hmma_kernel<0><<<dim3(Rr/128, Vv/128), 256, SMEMB>>>(
        hh, hl, w2h, w2l, b2, glin, nullptr, nullptr, HLh, Vv);
    // 10) loc_logits = h2 @ lw2 + lb2
    hmma_kernel<0><<<dim3(Rr/128, Vv/128), 256, SMEMB>>>(
        h2h, h2l, lw2h, lw2l, lb2, gloc, nullptr, nullptr, HCh, Vv);
    // 11) stats, gate, mix
    stats_kernel<<<dim3(Rr, 2), 256>>>();
    gate_kernel<<<(Rr + 255)/256, 256>>>(gate_w, gate_b);
    mix_kernel<<<dim3(Vv/256, Rr), 256>>>(out);
}